// round 1
// baseline (speedup 1.0000x reference)
#include <cuda_runtime.h>
#include <cstdint>

#define BB   32
#define NNN  4096
#define EEE  8192
#define DDD  128
#define MTOT (BB * NNN)      // 131072 rows
#define EMSG (BB * EEE)      // 262144 messages

#define STRIDE_A 136         // padded row stride (floats) for A tiles in smem
#define SMEM_FLOATS (2 * 128 * STRIDE_A + 6144)
#define SMEM_BYTES  (SMEM_FLOATS * 4)

// 64 MB scratch for the aggregated messages (allowed: __device__ global array)
__device__ float g_agg[(size_t)MTOT * DDD];

// ---------------------------------------------------------------------------
// Kernel 1: zero the aggregation buffer (graph replays re-run this each time)
// ---------------------------------------------------------------------------
__global__ void zero_kernel() {
    size_t i = (size_t)blockIdx.x * blockDim.x + threadIdx.x;  // 4,194,304 float4s
    reinterpret_cast<float4*>(g_agg)[i] = make_float4(0.f, 0.f, 0.f, 0.f);
}

// ---------------------------------------------------------------------------
// Kernel 2: scatter-add messages into g_agg (one thread = one float4 of a msg)
// ---------------------------------------------------------------------------
__global__ void scatter_kernel(const float* __restrict__ msgs,
                               const int* __restrict__ conn) {
    unsigned u = blockIdx.x * blockDim.x + threadIdx.x;  // EMSG*32 threads
    unsigned m = u >> 5;        // message index (b*E + e)
    unsigned l = u & 31;        // float4 lane within the 128-wide row
    int b = (int)(m >> 13);     // / E (8192)
    int tgt = __ldg(&conn[2 * m + 1]);
    float4 v = reinterpret_cast<const float4*>(msgs)[(size_t)m * 32 + l];
    size_t off = ((size_t)((b << 12) + tgt)) * DDD + l * 4;
    atomicAdd(&g_agg[off + 0], v.x);
    atomicAdd(&g_agg[off + 1], v.y);
    atomicAdd(&g_agg[off + 2], v.z);
    atomicAdd(&g_agg[off + 3], v.w);
}

// ---------------------------------------------------------------------------
// Kernel 3: fused dual-GEMM (tf32 mma.sync) + GRU gating epilogue
// CTA = 256 threads (8 warps), tile M=128 rows. Warp w owns m16 strip w.
// Loop over 16 n-blocks of 8 gate-columns; per block each warp computes the
// 6 accumulators (W1/W2 x z/r/h gates) -> thread-local GRU epilogue.
// ---------------------------------------------------------------------------
#define MMA8(ac, A0, A1, A2, A3, B0, B1)                                       \
    asm volatile(                                                              \
        "mma.sync.aligned.m16n8k8.row.col.f32.tf32.tf32.f32 "                  \
        "{%0,%1,%2,%3},{%4,%5,%6,%7},{%8,%9},{%0,%1,%2,%3};"                   \
        : "+f"(ac[0]), "+f"(ac[1]), "+f"(ac[2]), "+f"(ac[3])                   \
        : "r"(A0), "r"(A1), "r"(A2), "r"(A3), "r"(B0), "r"(B1))

__device__ __forceinline__ uint32_t f2tf32(float x) {
    uint32_t r;
    asm("cvt.rna.tf32.f32 %0, %1;" : "=r"(r) : "f"(x));
    return r;
}

__global__ void __launch_bounds__(256, 1) fused_gru_kernel(
    const float* __restrict__ H,      // atom_state, [MTOT][128]
    const float* __restrict__ W1,     // kernel, [128][384]
    const float* __restrict__ W2,     // recurrent_kernel, [128][384]
    const float* __restrict__ bias,   // [2][384]
    float* __restrict__ out)          // [MTOT][128]
{
    extern __shared__ uint32_t sm[];
    uint32_t* A1s = sm;                        // [128][STRIDE_A] tf32 (agg)
    uint32_t* A2s = sm + 128 * STRIDE_A;       // [128][STRIDE_A] tf32 (h)
    uint32_t* Bs  = sm + 2 * 128 * STRIDE_A;   // 6144 tf32 weight chunk

    const int tid  = threadIdx.x;
    const int warp = tid >> 5;
    const int lane = tid & 31;
    const int g    = lane >> 2;   // group id (row within m16 quad-group)
    const int t    = lane & 3;    // thread in group
    const size_t rowBase = (size_t)blockIdx.x * 128;

    // --- Stage A tiles: tf32-convert, k-permuted so (k, k+4) pairs are
    //     adjacent -> fragment loads become conflict-free LDS.64.
    //     k = o*8 + tt + 4p  stored at row*STRIDE_A + o*8 + 2*tt + p.
    for (int idx = tid; idx < 128 * 128; idx += 256) {
        int row = idx >> 7, k = idx & 127;
        int o = k >> 3, tt = k & 3, p = (k >> 2) & 1;
        int pos = row * STRIDE_A + o * 8 + tt * 2 + p;
        A1s[pos] = f2tf32(g_agg[(rowBase + row) * DDD + k]);
        A2s[pos] = f2tf32(H[(rowBase + row) * DDD + k]);
    }

    const int r0 = warp * 16 + g;  // this thread's first accumulator row
    const float* b1p = bias;
    const float* b2p = bias + 384;

    for (int nblk = 0; nblk < 16; nblk++) {
        __syncthreads();  // A ready (iter 0) / Bs consumers done (iter > 0)

        // --- Cooperative load of weight chunk for this n-block.
        //     Layout: Bs[((mg*16 + o)*8 + n)*8 + 2*tt + p], k = o*8+tt+4p,
        //     mg = mat*3 + gate. Conflict-free LDS.64 b-fragments.
        for (int c = tid; c < 6144; c += 256) {
            int mat = c / 3072;
            int r   = c - mat * 3072;
            int k   = r / 24;
            int q   = r - k * 24;
            int gate = q >> 3, n = q & 7;
            const float* W = mat ? W2 : W1;
            float w = __ldg(&W[k * 384 + gate * 128 + nblk * 8 + n]);
            int o = k >> 3, tt = k & 3, p = (k >> 2) & 1;
            int mg = mat * 3 + gate;
            Bs[(((mg * 16 + o) * 8 + n) * 8) + tt * 2 + p] = f2tf32(w);
        }
        __syncthreads();

        float acc[6][4];
#pragma unroll
        for (int i = 0; i < 6; i++)
#pragma unroll
            for (int j = 0; j < 4; j++) acc[i][j] = 0.f;

#pragma unroll 4
        for (int o = 0; o < 16; o++) {
            // A fragments: {a0,a1,a2,a3} = {(r0,k+t),(r0+8,k+t),(r0,k+t+4),(r0+8,k+t+4)}
            uint2 a1lo = *reinterpret_cast<const uint2*>(&A1s[r0 * STRIDE_A + o * 8 + 2 * t]);
            uint2 a1hi = *reinterpret_cast<const uint2*>(&A1s[(r0 + 8) * STRIDE_A + o * 8 + 2 * t]);
            uint2 a2lo = *reinterpret_cast<const uint2*>(&A2s[r0 * STRIDE_A + o * 8 + 2 * t]);
            uint2 a2hi = *reinterpret_cast<const uint2*>(&A2s[(r0 + 8) * STRIDE_A + o * 8 + 2 * t]);
            uint2 bf[6];
#pragma unroll
            for (int mg = 0; mg < 6; mg++)
                bf[mg] = *reinterpret_cast<const uint2*>(
                    &Bs[((mg * 16 + o) * 8 + g) * 8 + 2 * t]);
            // W1 gates consume aggregated (A1), W2 gates consume h (A2)
            MMA8(acc[0], a1lo.x, a1hi.x, a1lo.y, a1hi.y, bf[0].x, bf[0].y);
            MMA8(acc[1], a1lo.x, a1hi.x, a1lo.y, a1hi.y, bf[1].x, bf[1].y);
            MMA8(acc[2], a1lo.x, a1hi.x, a1lo.y, a1hi.y, bf[2].x, bf[2].y);
            MMA8(acc[3], a2lo.x, a2hi.x, a2lo.y, a2hi.y, bf[3].x, bf[3].y);
            MMA8(acc[4], a2lo.x, a2hi.x, a2lo.y, a2hi.y, bf[4].x, bf[4].y);
            MMA8(acc[5], a2lo.x, a2hi.x, a2lo.y, a2hi.y, bf[5].x, bf[5].y);
        }

        // --- GRU epilogue: thread owns (r0, j0..j0+1) and (r0+8, j0..j0+1)
        int j0 = nblk * 8 + 2 * t;
#pragma unroll
        for (int half = 0; half < 2; half++) {
            size_t row = rowBase + r0 + half * 8;
            float2 h2 = *reinterpret_cast<const float2*>(&H[row * DDD + j0]);
            float o2[2];
#pragma unroll
            for (int cc = 0; cc < 2; cc++) {
                int j  = j0 + cc;
                int ai = half * 2 + cc;
                float xz = acc[0][ai] + b1p[j];
                float xr = acc[1][ai] + b1p[128 + j];
                float xh = acc[2][ai] + b1p[256 + j];
                float rz = acc[3][ai] + b2p[j];
                float rr = acc[4][ai] + b2p[128 + j];
                float rh = acc[5][ai] + b2p[256 + j];
                float z = 1.f / (1.f + __expf(-(xz + rz)));
                float r = 1.f / (1.f + __expf(-(xr + rr)));
                float e = __expf(2.f * (xh + r * rh));
                float hh = 1.f - 2.f / (e + 1.f);   // tanh
                float hv = (cc == 0) ? h2.x : h2.y;
                o2[cc] = z * hv + (1.f - z) * hh;
            }
            *reinterpret_cast<float2*>(&out[row * DDD + j0]) =
                make_float2(o2[0], o2[1]);
        }
    }
}

// ---------------------------------------------------------------------------
extern "C" void kernel_launch(void* const* d_in, const int* in_sizes, int n_in,
                              void* d_out, int out_size) {
    const float* atom = (const float*)d_in[0];
    const float* msgs = (const float*)d_in[1];
    const int*   conn = (const int*)d_in[2];
    const float* W1   = (const float*)d_in[3];
    const float* W2   = (const float*)d_in[4];
    const float* bias = (const float*)d_in[5];
    float* out = (float*)d_out;

    zero_kernel<<<16384, 256>>>();                 // 16.7M floats / (256*4)
    scatter_kernel<<<32768, 256>>>(msgs, conn);    // 262144 msgs * 32 thr

    cudaFuncSetAttribute(fused_gru_kernel,
                         cudaFuncAttributeMaxDynamicSharedMemorySize,
                         SMEM_BYTES);
    fused_gru_kernel<<<MTOT / 128, 256, SMEM_BYTES>>>(atom, W1, W2, bias, out);
}

// round 3
// speedup vs baseline: 1.1451x; 1.1451x over previous
#include <cuda_runtime.h>
#include <cstdint>

#define BB   32
#define NNN  4096
#define EEE  8192
#define DDD  128
#define MTOT (BB * NNN)      // 131072 rows
#define EMSG (BB * EEE)      // 262144 messages

#define STRIDE_A 136         // padded row stride (floats) for A tiles in smem
#define B_CHUNK  12288       // 6 mg * 16 o * 16 n * 8  (tf32 words per n-block-pair)
#define SMEM_FLOATS (2 * 128 * STRIDE_A + B_CHUNK)
#define SMEM_BYTES  (SMEM_FLOATS * 4)

// 64 MB scratch for the aggregated messages
__device__ float g_agg[(size_t)MTOT * DDD];

// ---------------------------------------------------------------------------
// Kernel 1: zero the aggregation buffer
// ---------------------------------------------------------------------------
__global__ void zero_kernel() {
    size_t i = (size_t)blockIdx.x * blockDim.x + threadIdx.x;  // 4,194,304 float4s
    reinterpret_cast<float4*>(g_agg)[i] = make_float4(0.f, 0.f, 0.f, 0.f);
}

// ---------------------------------------------------------------------------
// Kernel 2: scatter-add messages into g_agg.
// One warp = one message (32 lanes x float4 = 128 floats).
// red.global.add.v4.f32 (PTX 8.1+, sm_90+): one 16B reduction per lane ->
// 4x fewer L2 atomic ops and sector transactions than scalar atomicAdd.
// conn index loaded once per warp and shfl-broadcast.
// ---------------------------------------------------------------------------
__global__ void scatter_kernel(const float* __restrict__ msgs,
                               const int* __restrict__ conn) {
    unsigned u = blockIdx.x * blockDim.x + threadIdx.x;  // EMSG*32 threads
    unsigned m = u >> 5;        // message index (b*E + e); uniform per warp
    unsigned l = u & 31;        // float4 lane within the 128-wide row
    int b = (int)(m >> 13);     // / E (8192)
    int tgt = 0;
    if (l == 0) tgt = __ldg(&conn[2 * m + 1]);
    tgt = __shfl_sync(0xffffffffu, tgt, 0);
    float4 v = reinterpret_cast<const float4*>(msgs)[(size_t)m * 32 + l];
    float* p = &g_agg[((size_t)((b << 12) + tgt)) * DDD + l * 4];
    asm volatile("red.global.add.v4.f32 [%0], {%1,%2,%3,%4};"
                 :: "l"(p), "f"(v.x), "f"(v.y), "f"(v.z), "f"(v.w)
                 : "memory");
}

// ---------------------------------------------------------------------------
// Kernel 3: fused dual-GEMM (tf32 mma.sync) + GRU gating epilogue.
// CTA = 256 threads (8 warps), tile M=128 rows; warp w owns m16 strip w.
// 8 outer iterations, each covering a PAIR of 8-wide n-blocks (16 gate cols):
// A fragments amortize over 12 MMAs instead of 6 -> ~20% less LDS traffic,
// and half the __syncthreads.
// ---------------------------------------------------------------------------
#define MMA8(ac, A0, A1, A2, A3, B0, B1)                                       \
    asm volatile(                                                              \
        "mma.sync.aligned.m16n8k8.row.col.f32.tf32.tf32.f32 "                  \
        "{%0,%1,%2,%3},{%4,%5,%6,%7},{%8,%9},{%0,%1,%2,%3};"                   \
        : "+f"(ac[0]), "+f"(ac[1]), "+f"(ac[2]), "+f"(ac[3])                   \
        : "r"(A0), "r"(A1), "r"(A2), "r"(A3), "r"(B0), "r"(B1))

__device__ __forceinline__ uint32_t f2tf32(float x) {
    uint32_t r;
    asm("cvt.rna.tf32.f32 %0, %1;" : "=r"(r) : "f"(x));
    return r;
}

__global__ void __launch_bounds__(256, 1) fused_gru_kernel(
    const float* __restrict__ H,      // atom_state, [MTOT][128]
    const float* __restrict__ W1,     // kernel, [128][384]
    const float* __restrict__ W2,     // recurrent_kernel, [128][384]
    const float* __restrict__ bias,   // [2][384]
    float* __restrict__ out)          // [MTOT][128]
{
    extern __shared__ uint32_t sm[];
    uint32_t* A1s = sm;                        // [128][STRIDE_A] tf32 (agg)
    uint32_t* A2s = sm + 128 * STRIDE_A;       // [128][STRIDE_A] tf32 (h)
    uint32_t* Bs  = sm + 2 * 128 * STRIDE_A;   // B_CHUNK tf32 weight chunk

    const int tid  = threadIdx.x;
    const int warp = tid >> 5;
    const int lane = tid & 31;
    const int g    = lane >> 2;   // row-within-quad-group (0..7)
    const int t    = lane & 3;    // thread in group (0..3)
    const size_t rowBase = (size_t)blockIdx.x * 128;

    // --- Stage A tiles: tf32-convert, k-permuted so (k, k+4) pairs are
    //     adjacent -> fragment loads are conflict-free LDS.64.
    //     k = o*8 + tt + 4p  stored at row*STRIDE_A + o*8 + 2*tt + p.
    for (int idx = tid; idx < 128 * 128; idx += 256) {
        int row = idx >> 7, k = idx & 127;
        int o = k >> 3, tt = k & 3, p = (k >> 2) & 1;
        int pos = row * STRIDE_A + o * 8 + tt * 2 + p;
        A1s[pos] = f2tf32(g_agg[(rowBase + row) * DDD + k]);
        A2s[pos] = f2tf32(H[(rowBase + row) * DDD + k]);
    }

    const int r0 = warp * 16 + g;  // this thread's first accumulator row
    const float* b1p = bias;
    const float* b2p = bias + 384;

    for (int blk = 0; blk < 8; blk++) {
        __syncthreads();  // A ready (iter 0) / Bs consumers done (iter > 0)

        // --- Cooperative load of the 16-column weight chunk.
        //     Bs[((mg*16 + o)*16 + n)*8 + 2*tt + p], k = o*8+tt+4p,
        //     mg = mat*3 + gate, n in [0,16).
        for (int c = tid; c < B_CHUNK; c += 256) {
            int mat = c / 6144;
            int r   = c - mat * 6144;
            int k   = r / 48;
            int q   = r - k * 48;
            int gate = q >> 4, n = q & 15;
            const float* W = mat ? W2 : W1;
            float w = __ldg(&W[k * 384 + gate * 128 + blk * 16 + n]);
            int o = k >> 3, tt = k & 3, p = (k >> 2) & 1;
            int mg = mat * 3 + gate;
            Bs[(((mg * 16 + o) * 16 + n) * 8) + tt * 2 + p] = f2tf32(w);
        }
        __syncthreads();

        float acc[12][4];            // [n8*6 + mg][frag]
#pragma unroll
        for (int i = 0; i < 12; i++)
#pragma unroll
            for (int j = 0; j < 4; j++) acc[i][j] = 0.f;

#pragma unroll 4
        for (int o = 0; o < 16; o++) {
            uint2 a1lo = *reinterpret_cast<const uint2*>(&A1s[r0 * STRIDE_A + o * 8 + 2 * t]);
            uint2 a1hi = *reinterpret_cast<const uint2*>(&A1s[(r0 + 8) * STRIDE_A + o * 8 + 2 * t]);
            uint2 a2lo = *reinterpret_cast<const uint2*>(&A2s[r0 * STRIDE_A + o * 8 + 2 * t]);
            uint2 a2hi = *reinterpret_cast<const uint2*>(&A2s[(r0 + 8) * STRIDE_A + o * 8 + 2 * t]);
#pragma unroll
            for (int n8 = 0; n8 < 2; n8++) {
                uint2 bf[6];
#pragma unroll
                for (int mg = 0; mg < 6; mg++)
                    bf[mg] = *reinterpret_cast<const uint2*>(
                        &Bs[((mg * 16 + o) * 16 + n8 * 8 + g) * 8 + 2 * t]);
                float* a0 = acc[n8 * 6 + 0];
                MMA8(a0, a1lo.x, a1hi.x, a1lo.y, a1hi.y, bf[0].x, bf[0].y);
                float* a1 = acc[n8 * 6 + 1];
                MMA8(a1, a1lo.x, a1hi.x, a1lo.y, a1hi.y, bf[1].x, bf[1].y);
                float* a2 = acc[n8 * 6 + 2];
                MMA8(a2, a1lo.x, a1hi.x, a1lo.y, a1hi.y, bf[2].x, bf[2].y);
                float* a3 = acc[n8 * 6 + 3];
                MMA8(a3, a2lo.x, a2hi.x, a2lo.y, a2hi.y, bf[3].x, bf[3].y);
                float* a4 = acc[n8 * 6 + 4];
                MMA8(a4, a2lo.x, a2hi.x, a2lo.y, a2hi.y, bf[4].x, bf[4].y);
                float* a5 = acc[n8 * 6 + 5];
                MMA8(a5, a2lo.x, a2hi.x, a2lo.y, a2hi.y, bf[5].x, bf[5].y);
            }
        }

        // --- GRU epilogue: thread owns rows {r0, r0+8} x cols {j0, j0+1}
        //     for each n8 half.
#pragma unroll
        for (int n8 = 0; n8 < 2; n8++) {
            int j0 = blk * 16 + n8 * 8 + 2 * t;
#pragma unroll
            for (int half = 0; half < 2; half++) {
                size_t row = rowBase + r0 + half * 8;
                float2 h2 = *reinterpret_cast<const float2*>(&H[row * DDD + j0]);
                float o2[2];
#pragma unroll
                for (int cc = 0; cc < 2; cc++) {
                    int j  = j0 + cc;
                    int ai = half * 2 + cc;
                    float xz = acc[n8 * 6 + 0][ai] + b1p[j];
                    float xr = acc[n8 * 6 + 1][ai] + b1p[128 + j];
                    float xh = acc[n8 * 6 + 2][ai] + b1p[256 + j];
                    float rz = acc[n8 * 6 + 3][ai] + b2p[j];
                    float rr = acc[n8 * 6 + 4][ai] + b2p[128 + j];
                    float rh = acc[n8 * 6 + 5][ai] + b2p[256 + j];
                    float z = 1.f / (1.f + __expf(-(xz + rz)));
                    float r = 1.f / (1.f + __expf(-(xr + rr)));
                    float e = __expf(2.f * (xh + r * rh));
                    float hh = 1.f - 2.f / (e + 1.f);   // tanh
                    float hv = (cc == 0) ? h2.x : h2.y;
                    o2[cc] = z * hv + (1.f - z) * hh;
                }
                *reinterpret_cast<float2*>(&out[row * DDD + j0]) =
                    make_float2(o2[0], o2[1]);
            }
        }
    }
}

// ---------------------------------------------------------------------------
extern "C" void kernel_launch(void* const* d_in, const int* in_sizes, int n_in,
                              void* d_out, int out_size) {
    const float* atom = (const float*)d_in[0];
    const float* msgs = (const float*)d_in[1];
    const int*   conn = (const int*)d_in[2];
    const float* W1   = (const float*)d_in[3];
    const float* W2   = (const float*)d_in[4];
    const float* bias = (const float*)d_in[5];
    float* out = (float*)d_out;

    zero_kernel<<<16384, 256>>>();                 // 16.7M floats / (256*4)
    scatter_kernel<<<32768, 256>>>(msgs, conn);    // 262144 msgs * 32 lanes

    cudaFuncSetAttribute(fused_gru_kernel,
                         cudaFuncAttributeMaxDynamicSharedMemorySize,
                         SMEM_BYTES);
    fused_gru_kernel<<<MTOT / 128, 256, SMEM_BYTES>>>(atom, W1, W2, bias, out);
}

// round 8
// speedup vs baseline: 1.7833x; 1.5573x over previous
#include <cuda_runtime.h>
#include <cstdint>

#define BB   32
#define NNN  4096
#define EEE  8192
#define DDD  128
#define MTOT (BB * NNN)      // 131072 rows
#define EMSG (BB * EEE)      // 262144 messages

#define STRIDE_A 136         // padded row stride (floats) for A tiles in smem
#define B_CHUNK  12288       // 6 mg * 16 o * 16 n * 8 words per n-block-pair
#define SMEM_FLOATS (2 * 128 * STRIDE_A + B_CHUNK)
#define SMEM_BYTES  (SMEM_FLOATS * 4)

// Device scratch (allocation-free rule: __device__ globals)
__device__ float    g_agg[(size_t)MTOT * DDD];    // 64 MB aggregated messages
__device__ uint32_t g_wf[8 * B_CHUNK];            // fragment-layout tf32 weights (384 KB)

__device__ __forceinline__ uint32_t f2tf32(float x) {
    uint32_t r;
    asm("cvt.rna.tf32.f32 %0, %1;" : "=r"(r) : "f"(x));
    return r;
}

// ---------------------------------------------------------------------------
// Kernel 1: zero the aggregation buffer
// ---------------------------------------------------------------------------
__global__ void zero_kernel() {
    size_t i = (size_t)blockIdx.x * blockDim.x + threadIdx.x;  // 4,194,304 float4s
    reinterpret_cast<float4*>(g_agg)[i] = make_float4(0.f, 0.f, 0.f, 0.f);
}

// ---------------------------------------------------------------------------
// Kernel 2: one-time weight prep. For each (blk, c) write the tf32 word the
// fused kernel's smem chunk expects at position c, so the per-CTA B load is a
// pure linear float4 copy. c = ((mg*16 + o)*16 + n)*8 + 2*tt + p,
// k = o*8 + tt + 4p, mg = mat*3 + gate, col = gate*128 + blk*16 + n.
// ---------------------------------------------------------------------------
__global__ void wprep_kernel(const float* __restrict__ W1,
                             const float* __restrict__ W2) {
    int i = blockIdx.x * blockDim.x + threadIdx.x;   // 98304
    int blk = i / B_CHUNK;
    int c   = i - blk * B_CHUNK;
    int mg  = c >> 11;            // / 2048
    int rem = c & 2047;
    int o   = rem >> 7;
    int rem2 = rem & 127;
    int n   = rem2 >> 3;
    int q   = rem2 & 7;
    int tt  = q >> 1, p = q & 1;
    int k   = o * 8 + tt + 4 * p;
    int mat = mg / 3, gate = mg - mat * 3;
    const float* W = mat ? W2 : W1;
    g_wf[i] = f2tf32(__ldg(&W[k * 384 + gate * 128 + blk * 16 + n]));
}

// ---------------------------------------------------------------------------
// Kernel 3: scatter-add messages (one warp per message, v4 global red)
// ---------------------------------------------------------------------------
__global__ void scatter_kernel(const float* __restrict__ msgs,
                               const int* __restrict__ conn) {
    unsigned u = blockIdx.x * blockDim.x + threadIdx.x;  // EMSG*32 threads
    unsigned m = u >> 5, l = u & 31;
    int b = (int)(m >> 13);
    int tgt = 0;
    if (l == 0) tgt = __ldg(&conn[2 * m + 1]);
    tgt = __shfl_sync(0xffffffffu, tgt, 0);
    float4 v = reinterpret_cast<const float4*>(msgs)[(size_t)m * 32 + l];
    float* p = &g_agg[((size_t)((b << 12) + tgt)) * DDD + l * 4];
    asm volatile("red.global.add.v4.f32 [%0], {%1,%2,%3,%4};"
                 :: "l"(p), "f"(v.x), "f"(v.y), "f"(v.z), "f"(v.w) : "memory");
}

// ---------------------------------------------------------------------------
// Kernel 4: fused dual-GEMM (tf32 mma.sync) + GRU gating epilogue.
// CTA = 256 threads (8 warps), M=128 rows; 8 iterations x 16 gate-columns.
// ---------------------------------------------------------------------------
#define MMA8(ac, A0, A1, A2, A3, B0, B1)                                       \
    asm volatile(                                                              \
        "mma.sync.aligned.m16n8k8.row.col.f32.tf32.tf32.f32 "                  \
        "{%0,%1,%2,%3},{%4,%5,%6,%7},{%8,%9},{%0,%1,%2,%3};"                   \
        : "+f"(ac[0]), "+f"(ac[1]), "+f"(ac[2]), "+f"(ac[3])                   \
        : "r"(A0), "r"(A1), "r"(A2), "r"(A3), "r"(B0), "r"(B1))

__global__ void __launch_bounds__(256, 1) fused_gru_kernel(
    const float* __restrict__ H,      // atom_state, [MTOT][128]
    const float* __restrict__ bias,   // [2][384]
    float* __restrict__ out)          // [MTOT][128]
{
    extern __shared__ uint32_t sm[];
    uint32_t* A1s = sm;                        // [128][STRIDE_A] tf32 (agg)
    uint32_t* A2s = sm + 128 * STRIDE_A;       // [128][STRIDE_A] tf32 (h)
    uint32_t* Bs  = sm + 2 * 128 * STRIDE_A;   // B_CHUNK tf32 weight chunk

    const int tid  = threadIdx.x;
    const int warp = tid >> 5;
    const int lane = tid & 31;
    const int g    = lane >> 2;   // row-within-quad-group (0..7)
    const int t    = lane & 3;    // thread in group (0..3)
    const size_t rowBase = (size_t)blockIdx.x * 128;

    // --- Stage A tiles, vectorized: per 8-k group load 2 float4, convert,
    //     interleave into the k-permuted layout (pos 2*tt+p), 2 STS.128.
    //     store words: s even -> k=s/2 ; s odd -> k=4+(s-1)/2
    //     lo = {k0,k4,k1,k5}, hi = {k2,k6,k3,k7}
    for (int gi = tid; gi < 2048; gi += 256) {
        int row = gi >> 4, o = gi & 15;
        const float* pa = &g_agg[(rowBase + row) * DDD + o * 8];
        const float* ph = &H[(rowBase + row) * DDD + o * 8];
        float4 a0 = *reinterpret_cast<const float4*>(pa);
        float4 a1 = *reinterpret_cast<const float4*>(pa + 4);
        float4 h0 = *reinterpret_cast<const float4*>(ph);
        float4 h1 = *reinterpret_cast<const float4*>(ph + 4);
        uint32_t* d1 = &A1s[row * STRIDE_A + o * 8];
        uint32_t* d2 = &A2s[row * STRIDE_A + o * 8];
        uint4 lo, hi;
        lo.x = f2tf32(a0.x); lo.y = f2tf32(a1.x); lo.z = f2tf32(a0.y); lo.w = f2tf32(a1.y);
        hi.x = f2tf32(a0.z); hi.y = f2tf32(a1.z); hi.z = f2tf32(a0.w); hi.w = f2tf32(a1.w);
        *reinterpret_cast<uint4*>(d1)     = lo;
        *reinterpret_cast<uint4*>(d1 + 4) = hi;
        lo.x = f2tf32(h0.x); lo.y = f2tf32(h1.x); lo.z = f2tf32(h0.y); lo.w = f2tf32(h1.y);
        hi.x = f2tf32(h0.z); hi.y = f2tf32(h1.z); hi.z = f2tf32(h0.w); hi.w = f2tf32(h1.w);
        *reinterpret_cast<uint4*>(d2)     = lo;
        *reinterpret_cast<uint4*>(d2 + 4) = hi;
    }

    const int r0 = warp * 16 + g;  // this thread's first accumulator row
    const float* b1p = bias;
    const float* b2p = bias + 384;

    for (int blk = 0; blk < 8; blk++) {
        __syncthreads();  // A ready (iter 0) / Bs consumers done (iter > 0)

        // --- B chunk: pure linear float4 copy from pre-formatted g_wf
        {
            const uint4* src = reinterpret_cast<const uint4*>(&g_wf[blk * B_CHUNK]);
            uint4* dst = reinterpret_cast<uint4*>(Bs);
#pragma unroll
            for (int v = 0; v < 12; v++)
                dst[tid + v * 256] = __ldg(&src[tid + v * 256]);
        }
        __syncthreads();

        float acc[12][4];            // [n8*6 + mg][frag]
#pragma unroll
        for (int i = 0; i < 12; i++)
#pragma unroll
            for (int j = 0; j < 4; j++) acc[i][j] = 0.f;

#pragma unroll 4
        for (int o = 0; o < 16; o++) {
            uint2 a1lo = *reinterpret_cast<const uint2*>(&A1s[r0 * STRIDE_A + o * 8 + 2 * t]);
            uint2 a1hi = *reinterpret_cast<const uint2*>(&A1s[(r0 + 8) * STRIDE_A + o * 8 + 2 * t]);
            uint2 a2lo = *reinterpret_cast<const uint2*>(&A2s[r0 * STRIDE_A + o * 8 + 2 * t]);
            uint2 a2hi = *reinterpret_cast<const uint2*>(&A2s[(r0 + 8) * STRIDE_A + o * 8 + 2 * t]);
#pragma unroll
            for (int n8 = 0; n8 < 2; n8++) {
                uint2 bf[6];
#pragma unroll
                for (int mg = 0; mg < 6; mg++)
                    bf[mg] = *reinterpret_cast<const uint2*>(
                        &Bs[((mg * 16 + o) * 16 + n8 * 8 + g) * 8 + 2 * t]);
                float* a0 = acc[n8 * 6 + 0];
                MMA8(a0, a1lo.x, a1hi.x, a1lo.y, a1hi.y, bf[0].x, bf[0].y);
                float* a1 = acc[n8 * 6 + 1];
                MMA8(a1, a1lo.x, a1hi.x, a1lo.y, a1hi.y, bf[1].x, bf[1].y);
                float* a2 = acc[n8 * 6 + 2];
                MMA8(a2, a1lo.x, a1hi.x, a1lo.y, a1hi.y, bf[2].x, bf[2].y);
                float* a3 = acc[n8 * 6 + 3];
                MMA8(a3, a2lo.x, a2hi.x, a2lo.y, a2hi.y, bf[3].x, bf[3].y);
                float* a4 = acc[n8 * 6 + 4];
                MMA8(a4, a2lo.x, a2hi.x, a2lo.y, a2hi.y, bf[4].x, bf[4].y);
                float* a5 = acc[n8 * 6 + 5];
                MMA8(a5, a2lo.x, a2hi.x, a2lo.y, a2hi.y, bf[5].x, bf[5].y);
            }
        }

        // --- GRU epilogue: thread owns rows {r0, r0+8} x cols {j0, j0+1}
#pragma unroll
        for (int n8 = 0; n8 < 2; n8++) {
            int j0 = blk * 16 + n8 * 8 + 2 * t;
#pragma unroll
            for (int half = 0; half < 2; half++) {
                size_t row = rowBase + r0 + half * 8;
                float2 h2 = *reinterpret_cast<const float2*>(&H[row * DDD + j0]);
                float o2[2];
#pragma unroll
                for (int cc = 0; cc < 2; cc++) {
                    int j  = j0 + cc;
                    int ai = half * 2 + cc;
                    float xz = acc[n8 * 6 + 0][ai] + b1p[j];
                    float xr = acc[n8 * 6 + 1][ai] + b1p[128 + j];
                    float xh = acc[n8 * 6 + 2][ai] + b1p[256 + j];
                    float rz = acc[n8 * 6 + 3][ai] + b2p[j];
                    float rr = acc[n8 * 6 + 4][ai] + b2p[128 + j];
                    float rh = acc[n8 * 6 + 5][ai] + b2p[256 + j];
                    float z = 1.f / (1.f + __expf(-(xz + rz)));
                    float r = 1.f / (1.f + __expf(-(xr + rr)));
                    float e = __expf(2.f * (xh + r * rh));
                    float hh = 1.f - 2.f / (e + 1.f);   // tanh
                    float hv = (cc == 0) ? h2.x : h2.y;
                    o2[cc] = z * hv + (1.f - z) * hh;
                }
                *reinterpret_cast<float2*>(&out[row * DDD + j0]) =
                    make_float2(o2[0], o2[1]);
            }
        }
    }
}

// ---------------------------------------------------------------------------
extern "C" void kernel_launch(void* const* d_in, const int* in_sizes, int n_in,
                              void* d_out, int out_size) {
    const float* atom = (const float*)d_in[0];
    const float* msgs = (const float*)d_in[1];
    const int*   conn = (const int*)d_in[2];
    const float* W1   = (const float*)d_in[3];
    const float* W2   = (const float*)d_in[4];
    const float* bias = (const float*)d_in[5];
    float* out = (float*)d_out;

    zero_kernel<<<16384, 256>>>();
    wprep_kernel<<<384, 256>>>(W1, W2);
    scatter_kernel<<<32768, 256>>>(msgs, conn);

    cudaFuncSetAttribute(fused_gru_kernel,
                         cudaFuncAttributeMaxDynamicSharedMemorySize,
                         SMEM_BYTES);
    fused_gru_kernel<<<MTOT / 128, 256, SMEM_BYTES>>>(atom, bias, out);
}